// round 16
// baseline (speedup 1.0000x reference)
#include <cuda_runtime.h>
#include <cstdint>

#define Bn 4
#define Cn 64
#define Nn 16384
#define On 128
#define Kn 16
#define EPSf 1e-5f
#define NEGf 0.2f
#define FLT_NEG (-3.402823466e38f)
#define FLT_POS (3.402823466e38f)
#define PTS 32
#define QT 128
#define CT 128

// -------- scratch (__device__ globals) --------
__device__ __align__(16) float g_xt[Bn * Nn * Cn];       // fp32 (edge gather)
__device__ __align__(16) float g_ai[Bn * Nn * 2 * Cn];   // interleaved (hi,lo) tf32 pairs
__device__ __align__(16) float g_xn[Bn * Nn];            // 0.5*|x|^2
__device__ __align__(16) int   g_idx[Bn * Nn * Kn];
__device__ __align__(16) float g_w1[Cn * On];
__device__ __align__(16) float g_wd[Cn * On];
__device__ float g_scale[On];
__device__ float g_bias[On];

// ---------------- PTX helpers ----------------
__device__ __forceinline__ uint32_t smem_u32(const void* p) {
    uint32_t a;
    asm("{ .reg .u64 t; cvta.to.shared.u64 t, %1; cvt.u32.u64 %0, t; }" : "=r"(a) : "l"(p));
    return a;
}
__device__ __forceinline__ uint32_t f2tf(float x) {
    uint32_t r; asm("cvt.rna.tf32.f32 %0, %1;" : "=r"(r) : "f"(x)); return r;
}
__device__ __forceinline__ void mma_tf32(float* d, const uint32_t* a, const uint32_t* b) {
    asm volatile("mma.sync.aligned.m16n8k8.row.col.f32.tf32.tf32.f32 "
        "{%0,%1,%2,%3}, {%4,%5,%6,%7}, {%8,%9}, {%0,%1,%2,%3};"
        : "+f"(d[0]), "+f"(d[1]), "+f"(d[2]), "+f"(d[3])
        : "r"(a[0]), "r"(a[1]), "r"(a[2]), "r"(a[3]), "r"(b[0]), "r"(b[1]));
}
#define CP_ASYNC16(dst, src) \
    asm volatile("cp.async.cg.shared.global [%0], [%1], 16;" :: "r"(dst), "l"(src))
#define CP_COMMIT() asm volatile("cp.async.commit_group;" ::: "memory")
#define CP_WAIT1()  asm volatile("cp.async.wait_group 1;" ::: "memory")

__device__ __forceinline__ void fma2(unsigned long long& d, unsigned long long a, unsigned long long b) {
    asm("fma.rn.f32x2 %0, %1, %2, %0;" : "+l"(d) : "l"(a), "l"(b));
}
__device__ __forceinline__ unsigned long long pack2(float v) {
    unsigned long long r; asm("mov.b64 %0, {%1, %1};" : "=l"(r) : "f"(v)); return r;
}
__device__ __forceinline__ void unpack2(unsigned long long v, float& lo, float& hi) {
    asm("mov.b64 {%0, %1}, %2;" : "=f"(lo), "=f"(hi) : "l"(v));
}

// ---------------- weight / BN prep ----------------
__global__ void prep_kernel(const float* __restrict__ W,
                            const float* __restrict__ gamma,
                            const float* __restrict__ beta,
                            const float* __restrict__ bn_mean,
                            const float* __restrict__ bn_var) {
    int o = threadIdx.x;
    float sc = gamma[o] * rsqrtf(bn_var[o] + EPSf);
    g_scale[o] = sc;
    g_bias[o]  = beta[o] - bn_mean[o] * sc;
    for (int c = 0; c < Cn; c++) {
        float w1 = W[o * (2 * Cn) + c];
        float w2 = W[o * (2 * Cn) + Cn + c];
        g_w1[c * On + o] = w1;
        g_wd[c * On + o] = w2 - w1;
    }
}

// ---------------- transpose + interleaved tf32 hi/lo ----------------
__global__ void transpose_kernel(const float* __restrict__ x) {
    __shared__ float s[32][65];
    int b  = blockIdx.y;
    int nb = blockIdx.x * 32;
    int tx = threadIdx.x, ty = threadIdx.y;
    const float* xb = x + (size_t)b * Cn * Nn;
#pragma unroll
    for (int i = 0; i < 8; i++) {
        int c = ty * 8 + i;
        s[tx][c] = xb[(size_t)c * Nn + nb + tx];
    }
    __syncthreads();
    int t = ty * 32 + tx;
    int r = t >> 3;
    int c0 = (t & 7) * 8;
    size_t base  = ((size_t)b * Nn + nb + r) * Cn + c0;
    size_t base2 = ((size_t)b * Nn + nb + r) * (2 * Cn) + 2 * c0;
#pragma unroll
    for (int i = 0; i < 8; i++) {
        float v = s[r][c0 + i];
        g_xt[base + i] = v;
        uint32_t hb = f2tf(v);
        float hv = __uint_as_float(hb);
        g_ai[base2 + 2 * i]     = hv;
        g_ai[base2 + 2 * i + 1] = __uint_as_float(f2tf(v - hv));
    }
}

// ---------------- half squared norms ----------------
__global__ void norm_kernel(const float* __restrict__ x) {
    int n = blockIdx.x * blockDim.x + threadIdx.x;
    int b = blockIdx.y;
    const float* xb = x + (size_t)b * Cn * Nn + n;
    float s = 0.f;
#pragma unroll
    for (int c = 0; c < Cn; c++) { float v = xb[(size_t)c * Nn]; s += v * v; }
    g_xn[b * Nn + n] = 0.5f * s;
}

// ---------------- KNN: tf32 3-pass, 512 thr, 32x32 warp tiles ---------
// floats: AS[128][136] | BS[2][128][136] | NS[2][128] | STG[16][32*9]
#define ROW2 136
#define AS_FL (QT * ROW2)                    // 17408
#define BS_OFF AS_FL
#define BS_BUF (CT * ROW2)                   // 17408
#define NS_OFF (BS_OFF + 2 * BS_BUF)         // 52224
#define STG_OFF (NS_OFF + 2 * CT)            // 52480
#define KNN_SMEM_FLOATS (STG_OFF + 16 * 288) // 57088 fl = 228,352 B

__device__ __forceinline__ void prefetch_tile(uint32_t bs_u32, uint32_t ns_u32,
                                              const float* __restrict__ ai,
                                              const float* __restrict__ xn,
                                              int rowbase, int tid) {
#pragma unroll
    for (int i = 0; i < 8; i++) {
        int idx = tid + i * 512;                 // 0..4095 (128 rows x 32 chunks)
        int r = idx >> 5, c = idx & 31;
        CP_ASYNC16(bs_u32 + (uint32_t)(r * (ROW2 * 4) + c * 16),
                   ai + (size_t)(rowbase + r) * (2 * Cn) + c * 4);
    }
    if (tid < 32)
        CP_ASYNC16(ns_u32 + (uint32_t)tid * 16, xn + rowbase + tid * 4);
}

__global__ __launch_bounds__(512, 1) void knn_kernel() {
    extern __shared__ __align__(16) float sh[];
    const float* ASp = sh;
    float* NS  = sh + NS_OFF;
    const uint32_t as_u = smem_u32(sh);
    const uint32_t bs_u = smem_u32(sh + BS_OFF);
    const uint32_t ns_u = smem_u32(NS);

    const int tid = threadIdx.x;
    const int wid = tid >> 5, lane = tid & 31;
    const int g = lane >> 2, t4 = lane & 3;
    const int warp_m = wid >> 2;           // 0..3 -> 32 query rows
    const int warp_n = wid & 3;            // 0..3 -> 32 cand cols
    const int m0 = warp_m * 32, n0 = warp_n * 32;

    const int b = blockIdx.x >> 7;
    const int qbase = (blockIdx.x & 127) << 7;
    const float* ai = g_ai + (size_t)b * Nn * (2 * Cn);
    const float* xn = g_xn + (size_t)b * Nn;

    // load A (128 rows x 32 chunks) + tiles 0,1
#pragma unroll
    for (int i = 0; i < 8; i++) {
        int idx = tid + i * 512;
        int r = idx >> 5, c = idx & 31;
        CP_ASYNC16(as_u + (uint32_t)(r * (ROW2 * 4) + c * 16),
                   ai + (size_t)(qbase + r) * (2 * Cn) + c * 4);
    }
    prefetch_tile(bs_u, ns_u, ai, xn, 0, tid);
    CP_COMMIT();
    prefetch_tile(bs_u + BS_BUF * 4, ns_u + CT * 4, ai, xn, CT, tid);
    CP_COMMIT();

    // selection state: each thread owns one query row (within warp_n quarter)
    float vtop[Kn]; int itop[Kn];
#pragma unroll
    for (int u = 0; u < Kn; u++) { vtop[u] = FLT_NEG; itop[u] = 0; }
    float vmin = FLT_NEG; int smin = 0;
    const int myrow = 16 * (t4 >> 1) + 8 * (t4 & 1) + g;   // 0..31
    const int qi = qbase + m0 + myrow;
    float* stg = sh + STG_OFF + wid * 288;

#pragma unroll 1
    for (int t = 0; t < Nn / CT; t++) {
        CP_WAIT1();
        __syncthreads();

        const float* Bbuf = sh + BS_OFF + (t & 1) * BS_BUF;
        const float* nsb  = NS + (t & 1) * CT;

        float acc[2][4][4];
#pragma unroll
        for (int mt = 0; mt < 2; mt++)
#pragma unroll
            for (int nt = 0; nt < 4; nt++)
#pragma unroll
                for (int r = 0; r < 4; r++) acc[mt][nt][r] = 0.f;

#pragma unroll
        for (int k8 = 0; k8 < 8; k8++) {
            const int kk2 = 2 * (8 * k8 + t4);
            uint32_t ah[2][4], al[2][4];
#pragma unroll
            for (int mt = 0; mt < 2; mt++) {
                const float* rb = ASp + (m0 + 16 * mt + g) * ROW2;
                float2 v0 = *(const float2*)(rb + kk2);
                float2 v1 = *(const float2*)(rb + 8 * ROW2 + kk2);
                float2 v2 = *(const float2*)(rb + kk2 + 8);
                float2 v3 = *(const float2*)(rb + 8 * ROW2 + kk2 + 8);
                ah[mt][0] = __float_as_uint(v0.x); al[mt][0] = __float_as_uint(v0.y);
                ah[mt][1] = __float_as_uint(v1.x); al[mt][1] = __float_as_uint(v1.y);
                ah[mt][2] = __float_as_uint(v2.x); al[mt][2] = __float_as_uint(v2.y);
                ah[mt][3] = __float_as_uint(v3.x); al[mt][3] = __float_as_uint(v3.y);
            }
#pragma unroll
            for (int nt = 0; nt < 4; nt++) {
                const float* rbB = Bbuf + (n0 + nt * 8 + g) * ROW2;
                float2 w0 = *(const float2*)(rbB + kk2);
                float2 w1 = *(const float2*)(rbB + kk2 + 8);
                uint32_t bh[2] = { __float_as_uint(w0.x), __float_as_uint(w1.x) };
                uint32_t bl[2] = { __float_as_uint(w0.y), __float_as_uint(w1.y) };
#pragma unroll
                for (int mt = 0; mt < 2; mt++) {
                    mma_tf32(acc[mt][nt], ah[mt], bh);
                    mma_tf32(acc[mt][nt], al[mt], bh);
                    mma_tf32(acc[mt][nt], ah[mt], bl);
                }
            }
        }

        // four 8-col phases per warp: private spill + select (syncwarp only)
#pragma unroll
        for (int ph = 0; ph < 4; ph++) {
            float nv0 = nsb[n0 + ph * 8 + 2 * t4];
            float nv1 = nsb[n0 + ph * 8 + 2 * t4 + 1];
#pragma unroll
            for (int mt = 0; mt < 2; mt++) {
                int rl = 16 * mt + g;
                stg[rl * 9 + 2 * t4]           = acc[mt][ph][0] - nv0;
                stg[rl * 9 + 2 * t4 + 1]       = acc[mt][ph][1] - nv1;
                stg[(rl + 8) * 9 + 2 * t4]     = acc[mt][ph][2] - nv0;
                stg[(rl + 8) * 9 + 2 * t4 + 1] = acc[mt][ph][3] - nv1;
            }
            __syncwarp();
            const int jg0 = t * CT + n0 + ph * 8;
            const float* srow = stg + myrow * 9;
#pragma unroll
            for (int c = 0; c < 8; c++) {
                float sv = srow[c];
                if (sv > vmin) {
                    int jg = jg0 + c;
                    if (jg != qi) {
                        vtop[smin] = sv; itop[smin] = jg;
                        float m = vtop[0]; int sm = 0;
#pragma unroll
                        for (int u = 1; u < Kn; u++)
                            if (vtop[u] < m) { m = vtop[u]; sm = u; }
                        vmin = m; smin = sm;
                    }
                }
            }
            __syncwarp();
        }

        // all reads of slot (t&1) done -> safe to refill for t+2
        __syncthreads();
        if (t + 2 < Nn / CT)
            prefetch_tile(bs_u + (uint32_t)(t & 1) * (BS_BUF * 4),
                          ns_u + (uint32_t)(t & 1) * (CT * 4),
                          ai, xn, (t + 2) * CT, tid);
        CP_COMMIT();
    }

    // merge the four warp_n partials per query (reuse BS region)
    __syncthreads();
    float* mv = sh + BS_OFF;                       // 3*128*16 = 6144 fl
    int*   mi = (int*)(sh + BS_OFF + 6144);
    const int qslot = m0 + myrow;                  // 0..127
    if (warp_n > 0) {
        int base = ((warp_n - 1) * QT + qslot) * Kn;
#pragma unroll
        for (int u = 0; u < Kn; u++) { mv[base + u] = vtop[u]; mi[base + u] = itop[u]; }
    }
    __syncthreads();
    if (warp_n == 0) {
        for (int hh = 0; hh < 3; hh++) {
            int base = (hh * QT + qslot) * Kn;
#pragma unroll
            for (int u = 0; u < Kn; u++) {
                float sv = mv[base + u];
                if (sv > vmin) {
                    vtop[smin] = sv; itop[smin] = mi[base + u];
                    float m = vtop[0]; int sm = 0;
#pragma unroll
                    for (int w = 1; w < Kn; w++)
                        if (vtop[w] < m) { m = vtop[w]; sm = w; }
                    vmin = m; smin = sm;
                }
            }
        }
        int* op = g_idx + ((size_t)b * Nn + qi) * Kn;
#pragma unroll
        for (int u = 0; u < Kn; u++) op[u] = itop[u];
    }
}

// ---------------- edge conv + BN + lrelu + max over k ----------------
#define EDGE_SMEM_FLOATS (Cn*On + 8*17*Cn + PTS*132 + 2*On)

__global__ __launch_bounds__(256, 2) void edge_kernel(float* __restrict__ out) {
    extern __shared__ float sm[];
    float* w1   = sm;
    float* feat = w1 + Cn * On;
    float* outs = feat + 8 * 17 * Cn;
    float* ssc  = outs + PTS * 132;
    float* sbi  = ssc + On;

    int tid = threadIdx.x, wid = tid >> 5, lane = tid & 31;

    for (int i = tid; i < Cn * On; i += 256) w1[i] = g_w1[i];
    if (tid < On) { ssc[tid] = g_scale[tid]; sbi[tid] = g_bias[tid]; }
    __syncthreads();

    int gp    = blockIdx.x * PTS;
    int b     = gp / Nn;
    int nbase = gp % Nn;
    const float* xtb = g_xt + (size_t)b * Nn * Cn;
    float* fw = feat + wid * 17 * Cn;
    int o0 = lane << 2;

#pragma unroll 1
    for (int pp = 0; pp < PTS / 8; pp++) {
        int pt = pp * 8 + wid;
        int n  = nbase + pt;

        const int* ip = g_idx + ((size_t)b * Nn + n) * Kn;
        int myid = (lane < Kn) ? ip[lane] : n;
#pragma unroll
        for (int r = 0; r < 18; r += 2) {
            int rr = r + (lane >> 4);
            int rowid = __shfl_sync(0xffffffffu, myid, rr & 31);
            if (rr >= Kn) rowid = n;
            if (rr < 17)
                ((float4*)(fw + rr * Cn))[lane & 15] =
                    ((const float4*)(xtb + (size_t)rowid * Cn))[lane & 15];
        }
        __syncwarp();

        float csv[4] = {0.f, 0.f, 0.f, 0.f};
        {
            const float* cen = fw + 16 * Cn;
#pragma unroll
            for (int c = 0; c < Cn; c++) {
                float e = cen[c];
                float4 wv = *(const float4*)(g_wd + c * On + o0);
                csv[0] += wv.x * e; csv[1] += wv.y * e;
                csv[2] += wv.z * e; csv[3] += wv.w * e;
            }
        }

        float mx[4] = {FLT_NEG, FLT_NEG, FLT_NEG, FLT_NEG};
        float mn[4] = {FLT_POS, FLT_POS, FLT_POS, FLT_POS};

#pragma unroll 1
        for (int k0 = 0; k0 < Kn; k0 += 4) {
            unsigned long long acc2[4][2];
#pragma unroll
            for (int j = 0; j < 4; j++) { acc2[j][0] = 0ull; acc2[j][1] = 0ull; }
            const float4* f0 = (const float4*)(fw + (k0 + 0) * Cn);
            const float4* f1 = (const float4*)(fw + (k0 + 1) * Cn);
            const float4* f2 = (const float4*)(fw + (k0 + 2) * Cn);
            const float4* f3 = (const float4*)(fw + (k0 + 3) * Cn);
#pragma unroll
            for (int c4 = 0; c4 < Cn / 4; c4++) {
                float4 e0 = f0[c4], e1 = f1[c4], e2 = f2[c4], e3 = f3[c4];
#pragma unroll
                for (int cc = 0; cc < 4; cc++) {
                    const float* wb = w1 + (c4 * 4 + cc) * On + o0;
                    unsigned long long wA = *(const unsigned long long*)wb;
                    unsigned long long wB = *(const unsigned long long*)(wb + 2);
                    float v0 = (cc == 0) ? e0.x : (cc == 1) ? e0.y : (cc == 2) ? e0.z : e0.w;
                    float v1 = (cc == 0) ? e1.x : (cc == 1) ? e1.y : (cc == 2) ? e1.z : e1.w;
                    float v2 = (cc == 0) ? e2.x : (cc == 1) ? e2.y : (cc == 2) ? e2.z : e2.w;
                    float v3 = (cc == 0) ? e3.x : (cc == 1) ? e3.y : (cc == 2) ? e3.z : e3.w;
                    unsigned long long p0 = pack2(v0), p1 = pack2(v1),
                                       p2 = pack2(v2), p3 = pack2(v3);
                    fma2(acc2[0][0], p0, wA); fma2(acc2[0][1], p0, wB);
                    fma2(acc2[1][0], p1, wA); fma2(acc2[1][1], p1, wB);
                    fma2(acc2[2][0], p2, wA); fma2(acc2[2][1], p2, wB);
                    fma2(acc2[3][0], p3, wA); fma2(acc2[3][1], p3, wB);
                }
            }
#pragma unroll
            for (int j = 0; j < 4; j++) {
                float a0, a1, a2, a3;
                unpack2(acc2[j][0], a0, a1);
                unpack2(acc2[j][1], a2, a3);
                mx[0] = fmaxf(mx[0], a0); mn[0] = fminf(mn[0], a0);
                mx[1] = fmaxf(mx[1], a1); mn[1] = fminf(mn[1], a1);
                mx[2] = fmaxf(mx[2], a2); mn[2] = fminf(mn[2], a2);
                mx[3] = fmaxf(mx[3], a3); mn[3] = fminf(mn[3], a3);
            }
        }

        float* od = outs + pt * 132 + o0;
#pragma unroll
        for (int r = 0; r < 4; r++) {
            float sc = ssc[o0 + r];
            float bi = sbi[o0 + r];
            float base = (sc > 0.f ? mx[r] : mn[r]) + csv[r];
            float yv = fmaf(sc, base, bi);
            yv = yv > 0.f ? yv : NEGf * yv;
            od[r] = yv;
        }
        __syncwarp();
    }

    __syncthreads();
    {
        int o = tid >> 1, h = tid & 1;
        float* dst = out + ((size_t)(b * On + o)) * Nn + nbase + h * 16;
#pragma unroll
        for (int i4 = 0; i4 < 4; i4++) {
            float4 vv;
            vv.x = outs[(h * 16 + i4 * 4 + 0) * 132 + o];
            vv.y = outs[(h * 16 + i4 * 4 + 1) * 132 + o];
            vv.z = outs[(h * 16 + i4 * 4 + 2) * 132 + o];
            vv.w = outs[(h * 16 + i4 * 4 + 3) * 132 + o];
            *(float4*)(dst + i4 * 4) = vv;
        }
    }
}

// ---------------- launch ----------------
extern "C" void kernel_launch(void* const* d_in, const int* in_sizes, int n_in,
                              void* d_out, int out_size) {
    const float* x       = (const float*)d_in[0];
    const float* W       = (const float*)d_in[1];
    const float* gamma   = (const float*)d_in[2];
    const float* beta    = (const float*)d_in[3];
    const float* bn_mean = (const float*)d_in[4];
    const float* bn_var  = (const float*)d_in[5];
    float* out = (float*)d_out;

    const size_t knn_smem  = KNN_SMEM_FLOATS * sizeof(float);
    const size_t edge_smem = EDGE_SMEM_FLOATS * sizeof(float);
    cudaFuncSetAttribute(knn_kernel, cudaFuncAttributeMaxDynamicSharedMemorySize,
                         (int)knn_smem);
    cudaFuncSetAttribute(edge_kernel, cudaFuncAttributeMaxDynamicSharedMemorySize,
                         (int)edge_smem);

    prep_kernel<<<1, On>>>(W, gamma, beta, bn_mean, bn_var);
    transpose_kernel<<<dim3(Nn / 32, Bn), dim3(32, 8)>>>(x);
    norm_kernel<<<dim3(Nn / 256, Bn), 256>>>(x);
    knn_kernel<<<Bn * (Nn / QT), 512, knn_smem>>>();
    edge_kernel<<<(Bn * Nn) / PTS, 256, edge_smem>>>(out);
}

// round 17
// speedup vs baseline: 1.2969x; 1.2969x over previous
#include <cuda_runtime.h>
#include <cstdint>

#define Bn 4
#define Cn 64
#define Nn 16384
#define On 128
#define Kn 16
#define EPSf 1e-5f
#define NEGf 0.2f
#define FLT_NEG (-3.402823466e38f)
#define FLT_POS (3.402823466e38f)
#define PTS 32
#define QT 128
#define CT 32
#define NTILES (Nn / CT)

// -------- scratch (__device__ globals) --------
__device__ __align__(16) float g_xt[Bn * Nn * Cn];       // fp32 (edge gather)
__device__ __align__(16) float g_ai[Bn * Nn * 2 * Cn];   // interleaved (hi,lo) tf32 pairs
__device__ __align__(16) float g_xn[Bn * Nn];            // 0.5*|x|^2
__device__ __align__(16) int   g_idx[Bn * Nn * Kn];
__device__ __align__(16) float g_w1[Cn * On];
__device__ __align__(16) float g_wd[Cn * On];
__device__ float g_scale[On];
__device__ float g_bias[On];

// ---------------- PTX helpers ----------------
__device__ __forceinline__ uint32_t smem_u32(const void* p) {
    uint32_t a;
    asm("{ .reg .u64 t; cvta.to.shared.u64 t, %1; cvt.u32.u64 %0, t; }" : "=r"(a) : "l"(p));
    return a;
}
__device__ __forceinline__ uint32_t f2tf(float x) {
    uint32_t r; asm("cvt.rna.tf32.f32 %0, %1;" : "=r"(r) : "f"(x)); return r;
}
__device__ __forceinline__ void mma_tf32(float* d, const uint32_t* a, const uint32_t* b) {
    asm volatile("mma.sync.aligned.m16n8k8.row.col.f32.tf32.tf32.f32 "
        "{%0,%1,%2,%3}, {%4,%5,%6,%7}, {%8,%9}, {%0,%1,%2,%3};"
        : "+f"(d[0]), "+f"(d[1]), "+f"(d[2]), "+f"(d[3])
        : "r"(a[0]), "r"(a[1]), "r"(a[2]), "r"(a[3]), "r"(b[0]), "r"(b[1]));
}
#define CP_ASYNC16(dst, src) \
    asm volatile("cp.async.cg.shared.global [%0], [%1], 16;" :: "r"(dst), "l"(src))
#define CP_COMMIT() asm volatile("cp.async.commit_group;" ::: "memory")
#define CP_WAIT0()  asm volatile("cp.async.wait_group 0;" ::: "memory")

#define MBAR_INIT(addr, cnt) \
    asm volatile("mbarrier.init.shared.b64 [%0], %1;" :: "r"(addr), "r"((uint32_t)(cnt)) : "memory")
#define MBAR_ARRIVE(addr) \
    asm volatile("mbarrier.arrive.shared.b64 _, [%0];" :: "r"(addr) : "memory")
#define CP_ASYNC_MBAR_ARRIVE(addr) \
    asm volatile("cp.async.mbarrier.arrive.noinc.shared.b64 [%0];" :: "r"(addr) : "memory")
#define MBAR_WAIT(addr, ph) do { \
    uint32_t _m = (addr); uint32_t _p = (ph); \
    asm volatile("{\n\t.reg .pred P1;\n\tWAIT_LOOP_%=:\n\t" \
        "mbarrier.try_wait.parity.acquire.cta.shared::cta.b64 P1, [%0], %1, 0x989680;\n\t" \
        "@P1 bra.uni WAIT_DONE_%=;\n\tbra.uni WAIT_LOOP_%=;\n\tWAIT_DONE_%=:\n\t}" \
        :: "r"(_m), "r"(_p) : "memory"); \
} while (0)

__device__ __forceinline__ void fma2(unsigned long long& d, unsigned long long a, unsigned long long b) {
    asm("fma.rn.f32x2 %0, %1, %2, %0;" : "+l"(d) : "l"(a), "l"(b));
}
__device__ __forceinline__ unsigned long long pack2(float v) {
    unsigned long long r; asm("mov.b64 %0, {%1, %1};" : "=l"(r) : "f"(v)); return r;
}
__device__ __forceinline__ void unpack2(unsigned long long v, float& lo, float& hi) {
    asm("mov.b64 {%0, %1}, %2;" : "=f"(lo), "=f"(hi) : "l"(v));
}

// ---------------- weight / BN prep ----------------
__global__ void prep_kernel(const float* __restrict__ W,
                            const float* __restrict__ gamma,
                            const float* __restrict__ beta,
                            const float* __restrict__ bn_mean,
                            const float* __restrict__ bn_var) {
    int o = threadIdx.x;
    float sc = gamma[o] * rsqrtf(bn_var[o] + EPSf);
    g_scale[o] = sc;
    g_bias[o]  = beta[o] - bn_mean[o] * sc;
    for (int c = 0; c < Cn; c++) {
        float w1 = W[o * (2 * Cn) + c];
        float w2 = W[o * (2 * Cn) + Cn + c];
        g_w1[c * On + o] = w1;
        g_wd[c * On + o] = w2 - w1;
    }
}

// ---------------- transpose + interleaved tf32 hi/lo ----------------
__global__ void transpose_kernel(const float* __restrict__ x) {
    __shared__ float s[32][65];
    int b  = blockIdx.y;
    int nb = blockIdx.x * 32;
    int tx = threadIdx.x, ty = threadIdx.y;
    const float* xb = x + (size_t)b * Cn * Nn;
#pragma unroll
    for (int i = 0; i < 8; i++) {
        int c = ty * 8 + i;
        s[tx][c] = xb[(size_t)c * Nn + nb + tx];
    }
    __syncthreads();
    int t = ty * 32 + tx;
    int r = t >> 3;
    int c0 = (t & 7) * 8;
    size_t base  = ((size_t)b * Nn + nb + r) * Cn + c0;
    size_t base2 = ((size_t)b * Nn + nb + r) * (2 * Cn) + 2 * c0;
#pragma unroll
    for (int i = 0; i < 8; i++) {
        float v = s[r][c0 + i];
        g_xt[base + i] = v;
        uint32_t hb = f2tf(v);
        float hv = __uint_as_float(hb);
        g_ai[base2 + 2 * i]     = hv;
        g_ai[base2 + 2 * i + 1] = __uint_as_float(f2tf(v - hv));
    }
}

// ---------------- half squared norms ----------------
__global__ void norm_kernel(const float* __restrict__ x) {
    int n = blockIdx.x * blockDim.x + threadIdx.x;
    int b = blockIdx.y;
    const float* xb = x + (size_t)b * Cn * Nn + n;
    float s = 0.f;
#pragma unroll
    for (int c = 0; c < Cn; c++) { float v = xb[(size_t)c * Nn]; s += v * v; }
    g_xn[b * Nn + n] = 0.5f * s;
}

// ---------- KNN: tf32 3-pass, producer/consumer mbarrier pipeline ------
// floats: AS[128][136] | BS[2][32][136] | NS[2][32] | STG[8][288] | MBAR(8fl)
#define ROW2 136
#define AS_FL (QT * ROW2)                   // 17408
#define BS_OFF AS_FL
#define BS_BUF (CT * ROW2)                  // 4352
#define NS_OFF (BS_OFF + 2 * BS_BUF)        // 26112
#define STG_OFF (NS_OFF + 2 * CT)           // 26176
#define MBAR_OFF (STG_OFF + 8 * 288)        // 28480 (byte off 113920, 8B aligned)
#define KNN_SMEM_FLOATS (MBAR_OFF + 8)      // 28488 fl = 113,952 B

__global__ __launch_bounds__(288, 2) void knn_kernel() {
    extern __shared__ __align__(16) float sh[];
    const float* ASp = sh;
    float* NS  = sh + NS_OFF;
    const uint32_t as_u = smem_u32(sh);
    const uint32_t bs_u = smem_u32(sh + BS_OFF);
    const uint32_t ns_u = smem_u32(NS);
    const uint32_t mb_u = smem_u32(sh + MBAR_OFF);
    // barriers: full0 @mb, full1 @mb+8, empty0 @mb+16, empty1 @mb+24

    const int tid = threadIdx.x;
    const int wid = tid >> 5, lane = tid & 31;
    const int g = lane >> 2, t4 = lane & 3;

    const int b = blockIdx.x >> 7;
    const int qbase = (blockIdx.x & 127) << 7;
    const float* ai = g_ai + (size_t)b * Nn * (2 * Cn);
    const float* xn = g_xn + (size_t)b * Nn;

    if (tid == 0) {
        MBAR_INIT(mb_u,      32);   // full0: 32 producer-lane async arrivals
        MBAR_INIT(mb_u + 8,  32);   // full1
        MBAR_INIT(mb_u + 16, 8);    // empty0: 8 consumer warps
        MBAR_INIT(mb_u + 24, 8);    // empty1
    }

    // cooperative A load (4096 16B chunks, 288 threads)
    for (int idx = tid; idx < 4096; idx += 288) {
        int r = idx >> 5, c = idx & 31;
        CP_ASYNC16(as_u + (uint32_t)(r * (ROW2 * 4) + c * 16),
                   ai + (size_t)(qbase + r) * (2 * Cn) + c * 4);
    }
    CP_COMMIT();
    CP_WAIT0();
    __syncthreads();   // A visible to all; mbarrier inits visible

    if (wid == 8) {
        // ---------------- producer warp ----------------
#pragma unroll 1
        for (int t = 0; t < NTILES; t++) {
            const uint32_t s = (uint32_t)(t & 1);
            if (t >= 2) MBAR_WAIT(mb_u + 16 + s * 8, ((uint32_t)(t >> 1) + 1u) & 1u);
            const uint32_t bdst = bs_u + s * (BS_BUF * 4);
            const float* src = ai + (size_t)(t * CT) * (2 * Cn);
#pragma unroll 4
            for (int i = lane; i < 1024; i += 32) {
                int r = i >> 5, c = i & 31;
                CP_ASYNC16(bdst + (uint32_t)(r * (ROW2 * 4) + c * 16),
                           src + (size_t)r * (2 * Cn) + c * 4);
            }
            if (lane < 8)
                CP_ASYNC16(ns_u + s * (CT * 4) + (uint32_t)lane * 16,
                           xn + t * CT + lane * 4);
            CP_ASYNC_MBAR_ARRIVE(mb_u + s * 8);   // full[s] when this lane's copies land
        }
    } else {
        // ---------------- consumer warps (R14 grid) ----------------
        const int warp_m = wid >> 1;           // 0..3
        const int warp_n = wid & 1;            // 0..1
        const int m0 = warp_m * 32;

        float vtop[Kn]; int itop[Kn];
#pragma unroll
        for (int u = 0; u < Kn; u++) { vtop[u] = FLT_NEG; itop[u] = 0; }
        float vmin = FLT_NEG; int smin = 0;
        const int myrow = 16 * (t4 >> 1) + 8 * (t4 & 1) + g;
        const int qi = qbase + m0 + myrow;
        float* stg = sh + STG_OFF + wid * 288;

#pragma unroll 1
        for (int t = 0; t < NTILES; t++) {
            const uint32_t s = (uint32_t)(t & 1);
            MBAR_WAIT(mb_u + s * 8, (uint32_t)(t >> 1) & 1u);

            const float* Bbuf = sh + BS_OFF + (t & 1) * BS_BUF;
            const float* nsb  = NS + (t & 1) * CT;

            float acc[2][2][4];
#pragma unroll
            for (int mt = 0; mt < 2; mt++)
#pragma unroll
                for (int nt = 0; nt < 2; nt++)
#pragma unroll
                    for (int r = 0; r < 4; r++) acc[mt][nt][r] = 0.f;

#pragma unroll
            for (int k8 = 0; k8 < 8; k8++) {
                const int kk2 = 2 * (8 * k8 + t4);
                uint32_t ah[2][4], al[2][4];
#pragma unroll
                for (int mt = 0; mt < 2; mt++) {
                    const float* rb = ASp + (m0 + 16 * mt + g) * ROW2;
                    float2 v0 = *(const float2*)(rb + kk2);
                    float2 v1 = *(const float2*)(rb + 8 * ROW2 + kk2);
                    float2 v2 = *(const float2*)(rb + kk2 + 8);
                    float2 v3 = *(const float2*)(rb + 8 * ROW2 + kk2 + 8);
                    ah[mt][0] = __float_as_uint(v0.x); al[mt][0] = __float_as_uint(v0.y);
                    ah[mt][1] = __float_as_uint(v1.x); al[mt][1] = __float_as_uint(v1.y);
                    ah[mt][2] = __float_as_uint(v2.x); al[mt][2] = __float_as_uint(v2.y);
                    ah[mt][3] = __float_as_uint(v3.x); al[mt][3] = __float_as_uint(v3.y);
                }
#pragma unroll
                for (int nt = 0; nt < 2; nt++) {
                    const float* rbB = Bbuf + (warp_n * 16 + nt * 8 + g) * ROW2;
                    float2 w0 = *(const float2*)(rbB + kk2);
                    float2 w1 = *(const float2*)(rbB + kk2 + 8);
                    uint32_t bh[2] = { __float_as_uint(w0.x), __float_as_uint(w1.x) };
                    uint32_t bl[2] = { __float_as_uint(w0.y), __float_as_uint(w1.y) };
#pragma unroll
                    for (int mt = 0; mt < 2; mt++) {
                        mma_tf32(acc[mt][nt], ah[mt], bh);
                        mma_tf32(acc[mt][nt], al[mt], bh);
                        mma_tf32(acc[mt][nt], ah[mt], bl);
                    }
                }
            }

            // per-warp spill + select (syncwarp only)
#pragma unroll
            for (int ph = 0; ph < 2; ph++) {
                float nv0 = nsb[warp_n * 16 + ph * 8 + 2 * t4];
                float nv1 = nsb[warp_n * 16 + ph * 8 + 2 * t4 + 1];
#pragma unroll
                for (int mt = 0; mt < 2; mt++) {
                    int rl = 16 * mt + g;
                    stg[rl * 9 + 2 * t4]           = acc[mt][ph][0] - nv0;
                    stg[rl * 9 + 2 * t4 + 1]       = acc[mt][ph][1] - nv1;
                    stg[(rl + 8) * 9 + 2 * t4]     = acc[mt][ph][2] - nv0;
                    stg[(rl + 8) * 9 + 2 * t4 + 1] = acc[mt][ph][3] - nv1;
                }
                __syncwarp();
                const int jg0 = t * CT + warp_n * 16 + ph * 8;
                const float* srow = stg + myrow * 9;
#pragma unroll
                for (int c = 0; c < 8; c++) {
                    float sv = srow[c];
                    if (sv > vmin) {
                        int jg = jg0 + c;
                        if (jg != qi) {
                            vtop[smin] = sv; itop[smin] = jg;
                            float m = vtop[0]; int sm = 0;
#pragma unroll
                            for (int u = 1; u < Kn; u++)
                                if (vtop[u] < m) { m = vtop[u]; sm = u; }
                            vmin = m; smin = sm;
                        }
                    }
                }
                __syncwarp();
            }

            if (lane == 0) MBAR_ARRIVE(mb_u + 16 + s * 8);   // release empty[s]
        }

        // stash partials for merge (warp_n==1)
        __syncwarp();
        if (warp_n == 1) {
            float* mv = sh + BS_OFF;
            int*   mi = (int*)(sh + BS_OFF + 2048);
            const int qslot = m0 + myrow;
#pragma unroll
            for (int u = 0; u < Kn; u++) {
                mv[qslot * Kn + u] = vtop[u];
                mi[qslot * Kn + u] = itop[u];
            }
        }

        __syncthreads();   // (1) all 288 threads
        if (warp_n == 0) {
            float* mv = sh + BS_OFF;
            int*   mi = (int*)(sh + BS_OFF + 2048);
            const int qslot = m0 + myrow;
#pragma unroll
            for (int u = 0; u < Kn; u++) {
                float sv = mv[qslot * Kn + u];
                if (sv > vmin) {
                    vtop[smin] = sv; itop[smin] = mi[qslot * Kn + u];
                    float m = vtop[0]; int sm = 0;
#pragma unroll
                    for (int w = 1; w < Kn; w++)
                        if (vtop[w] < m) { m = vtop[w]; sm = w; }
                    vmin = m; smin = sm;
                }
            }
            int* op = g_idx + ((size_t)b * Nn + qi) * Kn;
#pragma unroll
            for (int u = 0; u < Kn; u++) op[u] = itop[u];
        }
        return;
    }
    __syncthreads();       // (1) producer matches consumers' barrier
}

// ---------------- edge conv + BN + lrelu + max over k ----------------
#define EDGE_SMEM_FLOATS (Cn*On + 8*17*Cn + PTS*132 + 2*On)

__global__ __launch_bounds__(256, 2) void edge_kernel(float* __restrict__ out) {
    extern __shared__ float sm[];
    float* w1   = sm;
    float* feat = w1 + Cn * On;
    float* outs = feat + 8 * 17 * Cn;
    float* ssc  = outs + PTS * 132;
    float* sbi  = ssc + On;

    int tid = threadIdx.x, wid = tid >> 5, lane = tid & 31;

    for (int i = tid; i < Cn * On; i += 256) w1[i] = g_w1[i];
    if (tid < On) { ssc[tid] = g_scale[tid]; sbi[tid] = g_bias[tid]; }
    __syncthreads();

    int gp    = blockIdx.x * PTS;
    int b     = gp / Nn;
    int nbase = gp % Nn;
    const float* xtb = g_xt + (size_t)b * Nn * Cn;
    float* fw = feat + wid * 17 * Cn;
    int o0 = lane << 2;

#pragma unroll 1
    for (int pp = 0; pp < PTS / 8; pp++) {
        int pt = pp * 8 + wid;
        int n  = nbase + pt;

        const int* ip = g_idx + ((size_t)b * Nn + n) * Kn;
        int myid = (lane < Kn) ? ip[lane] : n;
#pragma unroll
        for (int r = 0; r < 18; r += 2) {
            int rr = r + (lane >> 4);
            int rowid = __shfl_sync(0xffffffffu, myid, rr & 31);
            if (rr >= Kn) rowid = n;
            if (rr < 17)
                ((float4*)(fw + rr * Cn))[lane & 15] =
                    ((const float4*)(xtb + (size_t)rowid * Cn))[lane & 15];
        }
        __syncwarp();

        float csv[4] = {0.f, 0.f, 0.f, 0.f};
        {
            const float* cen = fw + 16 * Cn;
#pragma unroll
            for (int c = 0; c < Cn; c++) {
                float e = cen[c];
                float4 wv = *(const float4*)(g_wd + c * On + o0);
                csv[0] += wv.x * e; csv[1] += wv.y * e;
                csv[2] += wv.z * e; csv[3] += wv.w * e;
            }
        }

        float mx[4] = {FLT_NEG, FLT_NEG, FLT_NEG, FLT_NEG};
        float mn[4] = {FLT_POS, FLT_POS, FLT_POS, FLT_POS};

#pragma unroll 1
        for (int k0 = 0; k0 < Kn; k0 += 4) {
            unsigned long long acc2[4][2];
#pragma unroll
            for (int j = 0; j < 4; j++) { acc2[j][0] = 0ull; acc2[j][1] = 0ull; }
            const float4* f0 = (const float4*)(fw + (k0 + 0) * Cn);
            const float4* f1 = (const float4*)(fw + (k0 + 1) * Cn);
            const float4* f2 = (const float4*)(fw + (k0 + 2) * Cn);
            const float4* f3 = (const float4*)(fw + (k0 + 3) * Cn);
#pragma unroll
            for (int c4 = 0; c4 < Cn / 4; c4++) {
                float4 e0 = f0[c4], e1 = f1[c4], e2 = f2[c4], e3 = f3[c4];
#pragma unroll
                for (int cc = 0; cc < 4; cc++) {
                    const float* wb = w1 + (c4 * 4 + cc) * On + o0;
                    unsigned long long wA = *(const unsigned long long*)wb;
                    unsigned long long wB = *(const unsigned long long*)(wb + 2);
                    float v0 = (cc == 0) ? e0.x : (cc == 1) ? e0.y : (cc == 2) ? e0.z : e0.w;
                    float v1 = (cc == 0) ? e1.x : (cc == 1) ? e1.y : (cc == 2) ? e1.z : e1.w;
                    float v2 = (cc == 0) ? e2.x : (cc == 1) ? e2.y : (cc == 2) ? e2.z : e2.w;
                    float v3 = (cc == 0) ? e3.x : (cc == 1) ? e3.y : (cc == 2) ? e3.z : e3.w;
                    unsigned long long p0 = pack2(v0), p1 = pack2(v1),
                                       p2 = pack2(v2), p3 = pack2(v3);
                    fma2(acc2[0][0], p0, wA); fma2(acc2[0][1], p0, wB);
                    fma2(acc2[1][0], p1, wA); fma2(acc2[1][1], p1, wB);
                    fma2(acc2[2][0], p2, wA); fma2(acc2[2][1], p2, wB);
                    fma2(acc2[3][0], p3, wA); fma2(acc2[3][1], p3, wB);
                }
            }
#pragma unroll
            for (int j = 0; j < 4; j++) {
                float a0, a1, a2, a3;
                unpack2(acc2[j][0], a0, a1);
                unpack2(acc2[j][1], a2, a3);
                mx[0] = fmaxf(mx[0], a0); mn[0] = fminf(mn[0], a0);
                mx[1] = fmaxf(mx[1], a1); mn[1] = fminf(mn[1], a1);
                mx[2] = fmaxf(mx[2], a2); mn[2] = fminf(mn[2], a2);
                mx[3] = fmaxf(mx[3], a3); mn[3] = fminf(mn[3], a3);
            }
        }

        float* od = outs + pt * 132 + o0;
#pragma unroll
        for (int r = 0; r < 4; r++) {
            float sc = ssc[o0 + r];
            float bi = sbi[o0 + r];
            float base = (sc > 0.f ? mx[r] : mn[r]) + csv[r];
            float yv = fmaf(sc, base, bi);
            yv = yv > 0.f ? yv : NEGf * yv;
            od[r] = yv;
        }
        __syncwarp();
    }

    __syncthreads();
    {
        int o = tid >> 1, h = tid & 1;
        float* dst = out + ((size_t)(b * On + o)) * Nn + nbase + h * 16;
#pragma unroll
        for (int i4 = 0; i4 < 4; i4++) {
            float4 vv;
            vv.x = outs[(h * 16 + i4 * 4 + 0) * 132 + o];
            vv.y = outs[(h * 16 + i4 * 4 + 1) * 132 + o];
            vv.z = outs[(h * 16 + i4 * 4 + 2) * 132 + o];
            vv.w = outs[(h * 16 + i4 * 4 + 3) * 132 + o];
            *(float4*)(dst + i4 * 4) = vv;
        }
    }
}

// ---------------- launch ----------------
extern "C" void kernel_launch(void* const* d_in, const int* in_sizes, int n_in,
                              void* d_out, int out_size) {
    const float* x       = (const float*)d_in[0];
    const float* W       = (const float*)d_in[1];
    const float* gamma   = (const float*)d_in[2];
    const float* beta    = (const float*)d_in[3];
    const float* bn_mean = (const float*)d_in[4];
    const float* bn_var  = (const float*)d_in[5];
    float* out = (float*)d_out;

    const size_t knn_smem  = KNN_SMEM_FLOATS * sizeof(float);
    const size_t edge_smem = EDGE_SMEM_FLOATS * sizeof(float);
    cudaFuncSetAttribute(knn_kernel, cudaFuncAttributeMaxDynamicSharedMemorySize,
                         (int)knn_smem);
    cudaFuncSetAttribute(edge_kernel, cudaFuncAttributeMaxDynamicSharedMemorySize,
                         (int)edge_smem);

    prep_kernel<<<1, On>>>(W, gamma, beta, bn_mean, bn_var);
    transpose_kernel<<<dim3(Nn / 32, Bn), dim3(32, 8)>>>(x);
    norm_kernel<<<dim3(Nn / 256, Bn), 256>>>(x);
    knn_kernel<<<Bn * (Nn / QT), 288, knn_smem>>>();
    edge_kernel<<<(Bn * Nn) / PTS, 256, edge_smem>>>(out);
}